// round 1
// baseline (speedup 1.0000x reference)
#include <cuda_runtime.h>
#include <cuda_bf16.h>

// NeRF renderer: 16384 rays, 64 coarse + 64 importance samples, 3->64->{1,3} MLP.
// One warp per ray. Lane-per-point MLP (no cross-lane reductions).

#define N_RAYS     16384
#define WARPS_PB   8
#define BLOCKS     (N_RAYS / WARPS_PB)

__device__ __forceinline__ float softplusf(float x) {
    return x > 20.0f ? x : log1pf(__expf(x));
}
__device__ __forceinline__ float sigmoidf(float x) {
    return 1.0f / (1.0f + __expf(-x));
}
__device__ __forceinline__ float clamp1(float x) {
    return fminf(fmaxf(x, -1.0f), 1.0f);
}

__global__ __launch_bounds__(256) void nerf_render_kernel(
    const float* __restrict__ rays_o,
    const float* __restrict__ rays_d,
    const float* __restrict__ W1,      // [3,64]
    const float* __restrict__ b1,      // [64]
    const float* __restrict__ w_sigma, // [64,1]
    const float* __restrict__ b_sigma, // [1]
    const float* __restrict__ W_rgb,   // [64,3]
    const float* __restrict__ b_rgb,   // [3]
    float* __restrict__ out)           // [N_RAYS,3]
{
    // Weights packed for vectorized broadcast loads:
    // sA[j] = {W1[0][j], W1[1][j], W1[2][j], b1[j]}
    // sB[j] = {w_sigma[j], W_rgb[j][0], W_rgb[j][1], W_rgb[j][2]}
    __shared__ float4 sA[64];
    __shared__ float4 sB[64];
    __shared__ float  sbias[4];            // b_sigma, b_rgb[0..2]
    __shared__ float  zc[WARPS_PB][64];    // coarse z
    __shared__ float  sbuf[WARPS_PB][64];  // coarse sigma -> cdf C[0..62]
    __shared__ float  wbuf[WARPS_PB][64];  // coarse weights -> new_z
    __shared__ float  zall[WARPS_PB][128];
    __shared__ float  sigall[WARPS_PB][128];
    __shared__ float  rgbs[WARPS_PB][3][128];

    const int tid = threadIdx.x;
    if (tid < 64) {
        sA[tid] = make_float4(W1[tid], W1[64 + tid], W1[128 + tid], b1[tid]);
        sB[tid] = make_float4(w_sigma[tid], W_rgb[3 * tid], W_rgb[3 * tid + 1], W_rgb[3 * tid + 2]);
    }
    if (tid == 64) {
        sbias[0] = b_sigma[0];
        sbias[1] = b_rgb[0];
        sbias[2] = b_rgb[1];
        sbias[3] = b_rgb[2];
    }
    __syncthreads();

    const int w    = tid >> 5;
    const int lane = tid & 31;
    const int ray  = blockIdx.x * WARPS_PB + w;

    // ---- ray setup (redundant across lanes) ----
    float ox = rays_o[3 * ray + 0], oy = rays_o[3 * ray + 1], oz = rays_o[3 * ray + 2];
    float dx = rays_d[3 * ray + 0], dy = rays_d[3 * ray + 1], dz = rays_d[3 * ray + 2];
    float inv = rsqrtf(dx * dx + dy * dy + dz * dz);
    dx *= inv; dy *= inv; dz *= inv;

    // near/far for [-1,1]^3 AABB
    float t0x = (-1.0f - ox) / (dx + 1e-15f), t1x = (1.0f - ox) / (dx + 1e-15f);
    float t0y = (-1.0f - oy) / (dy + 1e-15f), t1y = (1.0f - oy) / (dy + 1e-15f);
    float t0z = (-1.0f - oz) / (dz + 1e-15f), t1z = (1.0f - oz) / (dz + 1e-15f);
    float lox = fminf(t0x, t1x), hix = fmaxf(t0x, t1x);
    float loy = fminf(t0y, t1y), hiy = fmaxf(t0y, t1y);
    float loz = fminf(t0z, t1z), hiz = fmaxf(t0z, t1z);
    float near = fmaxf(lox, fmaxf(loy, loz));
    float far  = fminf(hix, fminf(hiy, hiz));
    if (far < near) { near = 1e9f; far = 1e9f; }
    near = fmaxf(near, 0.05f);
    float span = far - near;
    float sample_dist = span * (1.0f / 64.0f);

    // ---- coarse samples ----
    float z0 = near + span * ((float)lane * (1.0f / 63.0f));
    float z1 = near + span * ((float)(lane + 32) * (1.0f / 63.0f));
    zc[w][lane]      = z0;
    zc[w][lane + 32] = z1;

    float px0 = clamp1(ox + dx * z0), py0 = clamp1(oy + dy * z0), pz0 = clamp1(oz + dz * z0);
    float px1 = clamp1(ox + dx * z1), py1 = clamp1(oy + dy * z1), pz1 = clamp1(oz + dz * z1);
    float s0 = sbias[0], s1 = sbias[0];
    #pragma unroll 8
    for (int j = 0; j < 64; j++) {
        float4 a = sA[j];
        float wsj = sB[j].x;
        float h0 = fmaxf(0.0f, fmaf(px0, a.x, fmaf(py0, a.y, fmaf(pz0, a.z, a.w))));
        float h1 = fmaxf(0.0f, fmaf(px1, a.x, fmaf(py1, a.y, fmaf(pz1, a.z, a.w))));
        s0 = fmaf(h0, wsj, s0);
        s1 = fmaf(h1, wsj, s1);
    }
    sbuf[w][lane]      = softplusf(s0);
    sbuf[w][lane + 32] = softplusf(s1);
    __syncwarp();

    // ---- coarse alpha-composite weights (serial, lane 0) ----
    if (lane == 0) {
        float T = 1.0f;
        for (int t = 0; t < 64; t++) {
            float delta = (t < 63) ? (zc[w][t + 1] - zc[w][t]) : sample_dist;
            float a = 1.0f - __expf(-delta * sbuf[w][t]);
            wbuf[w][t] = a * T;
            T *= (1.0f - a + 1e-15f);
        }
        // cdf over weights[1..62] (+1e-5), normalized; C[0..62] overwrites sbuf
        float S = 0.0f;
        for (int i = 1; i <= 62; i++) S += wbuf[w][i] + 1e-5f;
        float invS = 1.0f / S;
        float run = 0.0f;
        sbuf[w][0] = 0.0f;
        for (int i = 0; i < 62; i++) {
            run += (wbuf[w][i + 1] + 1e-5f) * invS;
            sbuf[w][i + 1] = run;
        }
    }
    __syncwarp();

    // ---- inverse-CDF sampling: 64 deterministic u's ----
    #pragma unroll
    for (int p = 0; p < 2; p++) {
        int k = lane + 32 * p;
        float u = (float)(2 * k + 1) * (1.0f / 128.0f);
        // first idx in [0,63) with C[idx] > u  (C[0]=0 < u, so ind >= 1)
        int lo = 0, hi = 63;
        while (lo < hi) {
            int m = (lo + hi) >> 1;
            if (sbuf[w][m] > u) hi = m; else lo = m + 1;
        }
        int ind = lo;
        int below = ind - 1;
        int above = (ind > 62) ? 62 : ind;
        float cb = sbuf[w][below], ca = sbuf[w][above];
        float bb = 0.5f * (zc[w][below] + zc[w][below + 1]);
        float ba = 0.5f * (zc[w][above] + zc[w][above + 1]);
        float denom = ca - cb;
        if (denom < 1e-5f) denom = 1.0f;
        float nzv = bb + (u - cb) / denom * (ba - bb);
        wbuf[w][k] = nzv;  // wbuf now holds new_z (sorted)
    }
    __syncwarp();

    // ---- merge sorted zc[64] + new_z[64] -> zall[128] ----
    #pragma unroll
    for (int p = 0; p < 2; p++) {
        int t = lane + 32 * p;
        float v = zc[w][t];
        int lo = 0, hi = 64;           // count new_z < v
        while (lo < hi) { int m = (lo + hi) >> 1; if (wbuf[w][m] < v) lo = m + 1; else hi = m; }
        zall[w][t + lo] = v;
        float v2 = wbuf[w][t];
        int lo2 = 0, hi2 = 64;         // count zc <= v2
        while (lo2 < hi2) { int m = (lo2 + hi2) >> 1; if (zc[w][m] <= v2) lo2 = m + 1; else hi2 = m; }
        zall[w][t + lo2] = v2;
    }
    __syncwarp();

    // ---- fine MLP: 4 points per lane, sigma + rgb ----
    float fpx[4], fpy[4], fpz[4];
    float fs[4], fr[4], fg[4], fb[4];
    #pragma unroll
    for (int p = 0; p < 4; p++) {
        int t = lane + 32 * p;
        float z = zall[w][t];
        fpx[p] = clamp1(ox + dx * z);
        fpy[p] = clamp1(oy + dy * z);
        fpz[p] = clamp1(oz + dz * z);
        fs[p] = sbias[0];
        fr[p] = sbias[1];
        fg[p] = sbias[2];
        fb[p] = sbias[3];
    }
    #pragma unroll 4
    for (int j = 0; j < 64; j++) {
        float4 a = sA[j];
        float4 bw = sB[j];
        #pragma unroll
        for (int p = 0; p < 4; p++) {
            float h = fmaxf(0.0f, fmaf(fpx[p], a.x, fmaf(fpy[p], a.y, fmaf(fpz[p], a.z, a.w))));
            fs[p] = fmaf(h, bw.x, fs[p]);
            fr[p] = fmaf(h, bw.y, fr[p]);
            fg[p] = fmaf(h, bw.z, fg[p]);
            fb[p] = fmaf(h, bw.w, fb[p]);
        }
    }
    #pragma unroll
    for (int p = 0; p < 4; p++) {
        int t = lane + 32 * p;
        sigall[w][t]   = softplusf(fs[p]);
        rgbs[w][0][t]  = sigmoidf(fr[p]);
        rgbs[w][1][t]  = sigmoidf(fg[p]);
        rgbs[w][2][t]  = sigmoidf(fb[p]);
    }
    __syncwarp();

    // ---- final composite (serial, lane 0) ----
    if (lane == 0) {
        float T = 1.0f, wsum = 0.0f, i0 = 0.0f, i1 = 0.0f, i2 = 0.0f;
        for (int t = 0; t < 128; t++) {
            float delta = (t < 127) ? (zall[w][t + 1] - zall[w][t]) : sample_dist;
            float a = 1.0f - __expf(-delta * sigall[w][t]);
            float wt = a * T;
            i0 = fmaf(wt, rgbs[w][0][t], i0);
            i1 = fmaf(wt, rgbs[w][1][t], i1);
            i2 = fmaf(wt, rgbs[w][2][t], i2);
            wsum += wt;
            T *= (1.0f - a + 1e-15f);
        }
        float bg = 1.0f - wsum;
        out[3 * ray + 0] = i0 + bg;
        out[3 * ray + 1] = i1 + bg;
        out[3 * ray + 2] = i2 + bg;
    }
}

extern "C" void kernel_launch(void* const* d_in, const int* in_sizes, int n_in,
                              void* d_out, int out_size) {
    const float* rays_o  = (const float*)d_in[0];
    const float* rays_d  = (const float*)d_in[1];
    const float* W1      = (const float*)d_in[2];
    const float* b1      = (const float*)d_in[3];
    const float* w_sigma = (const float*)d_in[4];
    const float* b_sigma = (const float*)d_in[5];
    const float* W_rgb   = (const float*)d_in[6];
    const float* b_rgb   = (const float*)d_in[7];
    float* out = (float*)d_out;

    nerf_render_kernel<<<BLOCKS, 256>>>(rays_o, rays_d, W1, b1, w_sigma, b_sigma,
                                        W_rgb, b_rgb, out);
}

// round 2
// speedup vs baseline: 1.7540x; 1.7540x over previous
#include <cuda_runtime.h>
#include <cuda_bf16.h>

// NeRF renderer: 16384 rays, 64 coarse + 64 importance samples, 3->64->{1,3} MLP.
// One warp per ray. Contiguous chunk ownership; all scans are warp-parallel
// shuffle scans (no lane-0 serial loops).

#define N_RAYS     16384
#define WARPS_PB   8
#define BLOCKS     (N_RAYS / WARPS_PB)
#define FULLMASK   0xffffffffu

__device__ __forceinline__ float softplusf(float x) {
    return x > 20.0f ? x : __logf(1.0f + __expf(x));
}
__device__ __forceinline__ float sigmoidf(float x) {
    return __fdividef(1.0f, 1.0f + __expf(-x));
}
__device__ __forceinline__ float clamp1(float x) {
    return fminf(fmaxf(x, -1.0f), 1.0f);
}

__global__ __launch_bounds__(256) void nerf_render_kernel(
    const float* __restrict__ rays_o,
    const float* __restrict__ rays_d,
    const float* __restrict__ W1,      // [3,64]
    const float* __restrict__ b1,      // [64]
    const float* __restrict__ w_sigma, // [64,1]
    const float* __restrict__ b_sigma, // [1]
    const float* __restrict__ W_rgb,   // [64,3]
    const float* __restrict__ b_rgb,   // [3]
    float* __restrict__ out)           // [N_RAYS,3]
{
    // sA[j] = {W1[0][j], W1[1][j], W1[2][j], b1[j]}
    // sB[j] = {w_sigma[j], W_rgb[j][0], W_rgb[j][1], W_rgb[j][2]}
    __shared__ float4 sA[64];
    __shared__ float4 sB[64];
    __shared__ float  sWs[64];             // w_sigma scalar copy (coarse pass)
    __shared__ float  sbias[4];            // b_sigma, b_rgb[0..2]
    __shared__ float  zc[WARPS_PB][64];    // coarse z
    __shared__ float  cdfs[WARPS_PB][64];  // cdf C[0..62]
    __shared__ float  nz[WARPS_PB][64];    // new_z (sorted)
    __shared__ float  zall[WARPS_PB][128];

    const int tid = threadIdx.x;
    if (tid < 64) {
        sA[tid] = make_float4(W1[tid], W1[64 + tid], W1[128 + tid], b1[tid]);
        sB[tid] = make_float4(w_sigma[tid], W_rgb[3 * tid], W_rgb[3 * tid + 1], W_rgb[3 * tid + 2]);
        sWs[tid] = w_sigma[tid];
    }
    if (tid == 64) {
        sbias[0] = b_sigma[0];
        sbias[1] = b_rgb[0];
        sbias[2] = b_rgb[1];
        sbias[3] = b_rgb[2];
    }
    __syncthreads();

    const int w    = tid >> 5;
    const int lane = tid & 31;
    const int ray  = blockIdx.x * WARPS_PB + w;

    // ---- ray setup (redundant across lanes) ----
    float ox = rays_o[3 * ray + 0], oy = rays_o[3 * ray + 1], oz = rays_o[3 * ray + 2];
    float dx = rays_d[3 * ray + 0], dy = rays_d[3 * ray + 1], dz = rays_d[3 * ray + 2];
    float inv = rsqrtf(dx * dx + dy * dy + dz * dz);
    dx *= inv; dy *= inv; dz *= inv;

    float t0x = (-1.0f - ox) / (dx + 1e-15f), t1x = (1.0f - ox) / (dx + 1e-15f);
    float t0y = (-1.0f - oy) / (dy + 1e-15f), t1y = (1.0f - oy) / (dy + 1e-15f);
    float t0z = (-1.0f - oz) / (dz + 1e-15f), t1z = (1.0f - oz) / (dz + 1e-15f);
    float lox = fminf(t0x, t1x), hix = fmaxf(t0x, t1x);
    float loy = fminf(t0y, t1y), hiy = fmaxf(t0y, t1y);
    float loz = fminf(t0z, t1z), hiz = fmaxf(t0z, t1z);
    float near = fmaxf(lox, fmaxf(loy, loz));
    float far  = fminf(hix, fminf(hiy, hiz));
    if (far < near) { near = 1e9f; far = 1e9f; }
    near = fmaxf(near, 0.05f);
    float span = far - near;
    float sample_dist = span * (1.0f / 64.0f);
    float dcoarse = span * (1.0f / 63.0f);   // uniform coarse spacing

    // ---- coarse samples: lane owns t = 2*lane, 2*lane+1 (contiguous) ----
    int tc0 = 2 * lane;
    float z0 = near + span * ((float)tc0       * (1.0f / 63.0f));
    float z1 = near + span * ((float)(tc0 + 1) * (1.0f / 63.0f));
    zc[w][tc0]     = z0;
    zc[w][tc0 + 1] = z1;

    float px0 = clamp1(ox + dx * z0), py0 = clamp1(oy + dy * z0), pz0 = clamp1(oz + dz * z0);
    float px1 = clamp1(ox + dx * z1), py1 = clamp1(oy + dy * z1), pz1 = clamp1(oz + dz * z1);
    float s0 = sbias[0], s1 = sbias[0];
    #pragma unroll 8
    for (int j = 0; j < 64; j++) {
        float4 a = sA[j];
        float wsj = sWs[j];
        float h0 = fmaxf(0.0f, fmaf(px0, a.x, fmaf(py0, a.y, fmaf(pz0, a.z, a.w))));
        float h1 = fmaxf(0.0f, fmaf(px1, a.x, fmaf(py1, a.y, fmaf(pz1, a.z, a.w))));
        s0 = fmaf(h0, wsj, s0);
        s1 = fmaf(h1, wsj, s1);
    }
    float sig0 = softplusf(s0);
    float sig1 = softplusf(s1);

    // ---- coarse composite via warp product-scan ----
    // delta_t = dcoarse for t<63, sample_dist for t=63
    float d0 = dcoarse;
    float d1 = (lane == 31) ? sample_dist : dcoarse;
    float q0 = __expf(-d0 * sig0) + 1e-15f;
    float q1 = __expf(-d1 * sig1) + 1e-15f;
    float a0 = 1.0f - (q0 - 1e-15f);
    float a1 = 1.0f - (q1 - 1e-15f);

    float incl = q0 * q1;
    #pragma unroll
    for (int o = 1; o < 32; o <<= 1) {
        float t = __shfl_up_sync(FULLMASK, incl, o);
        if (lane >= o) incl *= t;
    }
    float Texcl = __shfl_up_sync(FULLMASK, incl, 1);
    if (lane == 0) Texcl = 1.0f;
    float w0 = a0 * Texcl;
    float w1 = a1 * Texcl * q0;

    // ---- CDF via warp add-scan over v_m, m=0..63 ----
    // v_m = (1 <= m <= 62) ? weights[m] + 1e-5 : 0
    float v0 = (lane > 0)  ? (w0 + 1e-5f) : 0.0f;
    float v1 = (lane < 31) ? (w1 + 1e-5f) : 0.0f;
    float lsum = v0 + v1;
    float sincl = lsum;
    #pragma unroll
    for (int o = 1; o < 32; o <<= 1) {
        float t = __shfl_up_sync(FULLMASK, sincl, o);
        if (lane >= o) sincl += t;
    }
    float sexcl = __shfl_up_sync(FULLMASK, sincl, 1);
    if (lane == 0) sexcl = 0.0f;
    float S = __shfl_sync(FULLMASK, sincl, 31);
    float invS = __fdividef(1.0f, S);
    cdfs[w][tc0]     = (sexcl + v0) * invS;
    cdfs[w][tc0 + 1] = (sexcl + lsum) * invS;
    __syncwarp();

    // ---- inverse-CDF sampling: 2 deterministic u's per lane ----
    #pragma unroll
    for (int p = 0; p < 2; p++) {
        int k = tc0 + p;
        float u = (float)(2 * k + 1) * (1.0f / 128.0f);
        int lo = 0, hi = 63;   // first idx in [0,63) with C[idx] > u
        while (lo < hi) {
            int m = (lo + hi) >> 1;
            if (cdfs[w][m] > u) hi = m; else lo = m + 1;
        }
        int ind = lo;
        int below = ind - 1;
        int above = (ind > 62) ? 62 : ind;
        float cb = cdfs[w][below], ca = cdfs[w][above];
        float bb = 0.5f * (zc[w][below] + zc[w][below + 1]);
        float ba = 0.5f * (zc[w][above] + zc[w][above + 1]);
        float denom = ca - cb;
        if (denom < 1e-5f) denom = 1.0f;
        nz[w][k] = bb + (u - cb) / denom * (ba - bb);
    }
    __syncwarp();

    // ---- merge sorted zc[64] + nz[64] -> zall[128] ----
    #pragma unroll
    for (int p = 0; p < 2; p++) {
        int t = tc0 + p;
        float v = zc[w][t];
        int lo = 0, hi = 64;           // count nz < v
        while (lo < hi) { int m = (lo + hi) >> 1; if (nz[w][m] < v) lo = m + 1; else hi = m; }
        zall[w][t + lo] = v;
        float v2 = nz[w][t];
        int lo2 = 0, hi2 = 64;         // count zc <= v2
        while (lo2 < hi2) { int m = (lo2 + hi2) >> 1; if (zc[w][m] <= v2) lo2 = m + 1; else hi2 = m; }
        zall[w][t + lo2] = v2;
    }
    __syncwarp();

    // ---- fine MLP: lane owns t = 4*lane .. 4*lane+3 (contiguous) ----
    float4 z4 = *reinterpret_cast<const float4*>(&zall[w][4 * lane]);
    float znext = (lane < 31) ? zall[w][4 * lane + 4] : 0.0f;

    float fpx[4], fpy[4], fpz[4];
    float fs[4], fr[4], fg[4], fb[4];
    float zr[4] = {z4.x, z4.y, z4.z, z4.w};
    #pragma unroll
    for (int p = 0; p < 4; p++) {
        fpx[p] = clamp1(ox + dx * zr[p]);
        fpy[p] = clamp1(oy + dy * zr[p]);
        fpz[p] = clamp1(oz + dz * zr[p]);
        fs[p] = sbias[0];
        fr[p] = sbias[1];
        fg[p] = sbias[2];
        fb[p] = sbias[3];
    }
    #pragma unroll 4
    for (int j = 0; j < 64; j++) {
        float4 a = sA[j];
        float4 bw = sB[j];
        #pragma unroll
        for (int p = 0; p < 4; p++) {
            float h = fmaxf(0.0f, fmaf(fpx[p], a.x, fmaf(fpy[p], a.y, fmaf(fpz[p], a.z, a.w))));
            fs[p] = fmaf(h, bw.x, fs[p]);
            fr[p] = fmaf(h, bw.y, fr[p]);
            fg[p] = fmaf(h, bw.z, fg[p]);
            fb[p] = fmaf(h, bw.w, fb[p]);
        }
    }

    float sg[4], qr[4], al[4];
    float dd[4];
    dd[0] = z4.y - z4.x;
    dd[1] = z4.z - z4.y;
    dd[2] = z4.w - z4.z;
    dd[3] = (lane < 31) ? (znext - z4.w) : sample_dist;
    #pragma unroll
    for (int p = 0; p < 4; p++) {
        sg[p] = softplusf(fs[p]);
        fr[p] = sigmoidf(fr[p]);
        fg[p] = sigmoidf(fg[p]);
        fb[p] = sigmoidf(fb[p]);
        qr[p] = __expf(-dd[p] * sg[p]) + 1e-15f;
        al[p] = 1.0f - (qr[p] - 1e-15f);
    }

    // ---- fine composite: warp product-scan of transmittance ----
    float fincl = (qr[0] * qr[1]) * (qr[2] * qr[3]);
    #pragma unroll
    for (int o = 1; o < 32; o <<= 1) {
        float t = __shfl_up_sync(FULLMASK, fincl, o);
        if (lane >= o) fincl *= t;
    }
    float T0 = __shfl_up_sync(FULLMASK, fincl, 1);
    if (lane == 0) T0 = 1.0f;
    float T1 = T0 * qr[0];
    float T2 = T1 * qr[1];
    float T3 = T2 * qr[2];

    float wt0 = al[0] * T0, wt1 = al[1] * T1, wt2 = al[2] * T2, wt3 = al[3] * T3;
    float wsum = (wt0 + wt1) + (wt2 + wt3);
    float i0 = fmaf(wt0, fr[0], fmaf(wt1, fr[1], fmaf(wt2, fr[2], wt3 * fr[3])));
    float i1 = fmaf(wt0, fg[0], fmaf(wt1, fg[1], fmaf(wt2, fg[2], wt3 * fg[3])));
    float i2 = fmaf(wt0, fb[0], fmaf(wt1, fb[1], fmaf(wt2, fb[2], wt3 * fb[3])));

    #pragma unroll
    for (int o = 16; o > 0; o >>= 1) {
        i0   += __shfl_xor_sync(FULLMASK, i0, o);
        i1   += __shfl_xor_sync(FULLMASK, i1, o);
        i2   += __shfl_xor_sync(FULLMASK, i2, o);
        wsum += __shfl_xor_sync(FULLMASK, wsum, o);
    }

    if (lane == 0) {
        float bg = 1.0f - wsum;
        out[3 * ray + 0] = i0 + bg;
        out[3 * ray + 1] = i1 + bg;
        out[3 * ray + 2] = i2 + bg;
    }
}

extern "C" void kernel_launch(void* const* d_in, const int* in_sizes, int n_in,
                              void* d_out, int out_size) {
    const float* rays_o  = (const float*)d_in[0];
    const float* rays_d  = (const float*)d_in[1];
    const float* W1      = (const float*)d_in[2];
    const float* b1      = (const float*)d_in[3];
    const float* w_sigma = (const float*)d_in[4];
    const float* b_sigma = (const float*)d_in[5];
    const float* W_rgb   = (const float*)d_in[6];
    const float* b_rgb   = (const float*)d_in[7];
    float* out = (float*)d_out;

    nerf_render_kernel<<<BLOCKS, 256>>>(rays_o, rays_d, W1, b1, w_sigma, b_sigma,
                                        W_rgb, b_rgb, out);
}